// round 14
// baseline (speedup 1.0000x reference)
#include <cuda_runtime.h>
#include <math.h>

#define NB 32
#define CH 256
#define HW 28
#define PIX (HW*HW)           // 784
#define PTOT (NB*PIX)         // 25088
#define NTOT (PTOT*CH)        // 6,422,528
#define WTOT (CH*CH*9)        // 589,824

// Eigen threaded-gemm k-panel: evaluateProductBlockingSizesHeuristic
// multi-thread branch caps k_cache at 320 (independent of L1 for l1>=16K).
#define KC 320

// ---------------- static scratch (no allocation) ---------------------------
__device__ __align__(16) float2 g_A1[NTOT];   // (x_msb, x_lsb) NHWC, layer1
__device__ __align__(16) float2 g_A2[NTOT];   // layer2
__device__ __align__(16) float  g_W1[WTOT];   // wq, [tap][c][k], tap = kh*3+kw
__device__ __align__(16) float  g_W2[WTOT];
__device__ __align__(16) float  g_out1[NTOT]; // relu(pgconv1) NHWC
__device__ unsigned int g_scal[4];            // 0=max|x| 1=max|w1| 2=max|w2| 3=max(out1)

// ---------------------------------------------------------------------------
__global__ void k_init() {
    if (threadIdx.x < 4) g_scal[threadIdx.x] = 0u;
}

__global__ void k_maxabs(const float* __restrict__ p, int n4, int slot) {
    float m = 0.f;
    for (int i = blockIdx.x * blockDim.x + threadIdx.x; i < n4; i += gridDim.x * blockDim.x) {
        float4 v = reinterpret_cast<const float4*>(p)[i];
        m = fmaxf(m, fmaxf(fmaxf(fabsf(v.x), fabsf(v.y)), fmaxf(fabsf(v.z), fabsf(v.w))));
    }
    for (int o = 16; o; o >>= 1) m = fmaxf(m, __shfl_xor_sync(0xffffffffu, m, o));
    if ((threadIdx.x & 31) == 0) atomicMax(&g_scal[slot], __float_as_uint(m));
}

// Mirror of (truncate_msb, quantize_bits, subtraction), reciprocal-multiply
// forms (divide -> multiply-by-reciprocal), per R12 (best variant so far).
__device__ __forceinline__ float2 quant_pair(float v, float S) {
    const float C127R = (float)(1.0 / 127.0);
    float a  = fabsf(v);
    float st = __fadd_rn(S, 1e-8f);
    float sr = __fadd_rn(S, 1e-7f);
    float rt = __fdiv_rn(1.0f, st);
    float rr = __fdiv_rn(1.0f, sr);
    float q1 = floorf(__fmul_rn(__fmul_rn(a, rt), 128.0f));
    float q2 = floorf(__fmul_rn(q1, 0.0625f));                 // /16 exact
    float q4 = __fmul_rn(__fmul_rn(q2, 16.0f), 0.0078125f);    // *16, /128 exact
    float xm = __fmul_rn(q4, st);
    float r  = rintf(__fmul_rn(__fmul_rn(a, rr), 127.0f));     // half-even
    float xq = __fmul_rn(__fmul_rn(r, C127R), sr);
    if (v < 0.0f) { xm = -xm; xq = -xq; }
    return make_float2(xm, __fsub_rn(xq, xm));
}

// x (NCHW f32) -> g_A1 (NHWC float2)
__global__ void k_quant_x(const float* __restrict__ x) {
    int i = blockIdx.x * blockDim.x + threadIdx.x;
    if (i >= NTOT) return;
    int c = i & 255, p = i >> 8;
    int n = p / PIX, q = p - n * PIX;
    float S = __uint_as_float(g_scal[0]);
    g_A1[i] = quant_pair(x[(n * CH + c) * PIX + q], S);
}

// relu(out1) (NHWC) -> g_A2
__global__ void k_quant_a() {
    int i = blockIdx.x * blockDim.x + threadIdx.x;
    if (i >= NTOT) return;
    float S = __uint_as_float(g_scal[3]);
    g_A2[i] = quant_pair(g_out1[i], S);
}

// w (OIHW f32) -> wq in [tap][c][k] layout, tap = kh*3+kw (kh-major)
__global__ void k_quant_w(const float* __restrict__ w, int slot, float* __restrict__ dst) {
    const float C127R = (float)(1.0 / 127.0);
    int e = blockIdx.x * blockDim.x + threadIdx.x;
    if (e >= WTOT) return;
    int k = e & 255, r = e >> 8;
    int c = r & 255, tap = r >> 8;
    float v = w[(k * CH + c) * 9 + tap];
    float s = __fadd_rn(__uint_as_float(g_scal[slot]), 1e-7f);
    float rs = __fdiv_rn(1.0f, s);
    float q = rintf(__fmul_rn(__fmul_rn(fabsf(v), rs), 127.0f));
    float wq = __fmul_rn(__fmul_rn(q, C127R), s);
    if (v < 0.0f) wq = -wq;
    dst[e] = wq;
}

// ------------------- packed f32x2 helpers (bitwise == scalar) --------------
__device__ __forceinline__ unsigned long long fma2(unsigned long long a,
                                                   unsigned long long b,
                                                   unsigned long long c) {
    unsigned long long d;
    asm("fma.rn.f32x2 %0, %1, %2, %3;" : "=l"(d) : "l"(a), "l"(b), "l"(c));
    return d;
}
__device__ __forceinline__ unsigned long long add2(unsigned long long a,
                                                   unsigned long long b) {
    unsigned long long d;
    asm("add.rn.f32x2 %0, %1, %2;" : "=l"(d) : "l"(a), "l"(b));
    return d;
}
__device__ __forceinline__ unsigned long long dupf(float w) {
    unsigned long long d;
    asm("mov.b64 %0, {%1, %2};" : "=l"(d) : "f"(w), "f"(w));
    return d;
}
__device__ __forceinline__ void unpack2(unsigned long long v, float& lo, float& hi) {
    asm("mov.b64 {%0, %1}, %2;" : "=f"(lo), "=f"(hi) : "l"(v));
}

// Gate: XLA logistic 0.5 + 0.5*tanh(0.5x), tanh = XLA f32 rational (proven
// interchangeable across all tested variants; kept fixed).
__device__ __forceinline__ bool gate(float msb) {
    float x = __fmul_rn(0.5f, msb);
    x = fminf(fmaxf(x, -7.90531110763549805f), 7.90531110763549805f);
    float x2 = __fmul_rn(x, x);
    float p = __fmaf_rn(x2, -2.76076847742355e-16f, 2.00018790482477e-13f);
    p = __fmaf_rn(x2, p, -8.60467152213735e-11f);
    p = __fmaf_rn(x2, p,  5.12229709037114e-08f);
    p = __fmaf_rn(x2, p,  1.48572235717979e-05f);
    p = __fmaf_rn(x2, p,  6.37261928875436e-04f);
    p = __fmaf_rn(x2, p,  4.89352455891786e-03f);
    float num = __fmul_rn(x, p);
    float q = __fmaf_rn(x2, 1.19825839466702e-06f, 1.18534705686654e-04f);
    q = __fmaf_rn(x2, q, 2.26843463243900e-03f);
    q = __fmaf_rn(x2, q, 4.89352518554385e-03f);
    float t = __fdiv_rn(num, q);
    float s = __fadd_rn(0.5f, __fmul_rn(0.5f, t));
    return s > 0.99f;
}

// ---------------------------------------------------------------------------
// Dual f32 conv mirroring Eigen THREADED tensor-contraction accumulation:
// gemm-K = (kh, kw, c-fastest) ascending; panels of kc = 320 (Eigen's
// multi-thread k_cache cap); each panel a serial FMA chain from zero; panels
// combined by ascending sequential fadd into the result.
// Panel boundaries at gemm-k = 320*p  =>  per-tap flush c* (tap = gemm-k/256):
//   tap:   0   1    2    3    4   5   6    7    8
//   c*:    -   64   128  192  -   0   64   128  192
// Block: 64 pixels x 128 k, 256 threads; thread tile 4 pix x 8 k; both convs
// (msb / lsb) packed per-lane in f32x2 (per-lane IEEE-RN == scalar).
// ---------------------------------------------------------------------------
template <int LAYER>
__global__ void __launch_bounds__(256) k_conv(const float2* __restrict__ Ain,
                                              const float* __restrict__ Win,
                                              const float* __restrict__ xres,
                                              float* __restrict__ outg) {
    __shared__ __align__(16) float2 sA[64][34];   // [pix][c] (xm, xd)
    __shared__ __align__(16) float  sB[32][132];  // [c][k]

    const int t = threadIdx.x, tx = t & 15, ty = t >> 4;
    const int ktile = blockIdx.x;                 // 0..1
    const int ptile = blockIdx.y;                 // 0..391

    const int lp = t >> 2, q4 = t & 3;
    const int gp = ptile * 64 + lp;
    const int n  = gp / PIX, q0 = gp - n * PIX;
    const int py = q0 / HW,  pxx = q0 - py * HW;
    const int crow = t >> 3, koff = (t & 7) * 16;

    unsigned long long acc[4][8], tot[4][8];
#pragma unroll
    for (int i = 0; i < 4; i++)
#pragma unroll
        for (int j = 0; j < 8; j++) { acc[i][j] = 0ull; tot[i][j] = 0ull; }

#pragma unroll 1
    for (int tap = 0; tap < 9; ++tap) {
        const int dy = tap / 3 - 1, dx = tap - (tap / 3) * 3 - 1;   // kh-major
        const int yy = py + dy, xx = pxx + dx;
        const bool valid = ((unsigned)yy < (unsigned)HW) && ((unsigned)xx < (unsigned)HW);
        const int srcbase = ((n * HW + yy) * HW + xx) * CH;
        // next multiple of KC at/after tap*256, as c-offset within this tap
        const int kb = tap * 256;
        const int cstar = ((kb + KC - 1) / KC) * KC - kb;           // {0,64,128,192,>=256}

#pragma unroll 1
        for (int cblk = 0; cblk < CH; cblk += 32) {
            float4 a0 = {0,0,0,0}, a1 = {0,0,0,0}, a2 = {0,0,0,0}, a3 = {0,0,0,0};
            if (valid) {
                const float4* src = reinterpret_cast<const float4*>(Ain + srcbase + cblk + q4 * 8);
                a0 = src[0]; a1 = src[1]; a2 = src[2]; a3 = src[3];
            }
            const float4* wsrc = reinterpret_cast<const float4*>(
                Win + (tap * CH + cblk + crow) * CH + ktile * 128 + koff);
            float4 b0 = wsrc[0], b1 = wsrc[1], b2 = wsrc[2], b3 = wsrc[3];

            __syncthreads();
            { float4* da = reinterpret_cast<float4*>(&sA[lp][q4 * 8]);
              da[0] = a0; da[1] = a1; da[2] = a2; da[3] = a3; }
            { float4* db = reinterpret_cast<float4*>(&sB[crow][koff]);
              db[0] = b0; db[1] = b1; db[2] = b2; db[3] = b3; }
            __syncthreads();

#pragma unroll
            for (int cp = 0; cp < 16; ++cp) {      // c-pairs, ascending (c fastest)
                if (cblk + 2 * cp == cstar) {      // kc=320 panel flush (uniform)
#pragma unroll
                    for (int i = 0; i < 4; ++i)
#pragma unroll
                        for (int j = 0; j < 8; ++j) {
                            tot[i][j] = add2(tot[i][j], acc[i][j]);
                            acc[i][j] = 0ull;
                        }
                }
                ulonglong2 av[4];
#pragma unroll
                for (int i = 0; i < 4; ++i)
                    av[i] = *reinterpret_cast<const ulonglong2*>(&sA[ty * 4 + i][2 * cp]);
                float w0[8], w1[8];
                *reinterpret_cast<float4*>(&w0[0]) = *reinterpret_cast<const float4*>(&sB[2*cp    ][tx*8    ]);
                *reinterpret_cast<float4*>(&w0[4]) = *reinterpret_cast<const float4*>(&sB[2*cp    ][tx*8 + 4]);
                *reinterpret_cast<float4*>(&w1[0]) = *reinterpret_cast<const float4*>(&sB[2*cp + 1][tx*8    ]);
                *reinterpret_cast<float4*>(&w1[4]) = *reinterpret_cast<const float4*>(&sB[2*cp + 1][tx*8 + 4]);
#pragma unroll
                for (int j = 0; j < 8; ++j) {
                    unsigned long long p0 = dupf(w0[j]);
                    unsigned long long p1 = dupf(w1[j]);
#pragma unroll
                    for (int i = 0; i < 4; ++i) {
                        acc[i][j] = fma2(av[i].x, p0, acc[i][j]);   // c even
                        acc[i][j] = fma2(av[i].y, p1, acc[i][j]);   // c odd
                    }
                }
            }
        }
    }

    // final partial panel (gemm-k 2240..2303, 64 terms)
#pragma unroll
    for (int i = 0; i < 4; ++i)
#pragma unroll
        for (int j = 0; j < 8; ++j) tot[i][j] = add2(tot[i][j], acc[i][j]);

    // ------------------------- epilogue ------------------------------------
    if (LAYER == 1) {
        float vmax = 0.f;
#pragma unroll
        for (int i = 0; i < 4; ++i) {
            const int p = ptile * 64 + ty * 4 + i;
            float o[8];
#pragma unroll
            for (int j = 0; j < 8; ++j) {
                float msb, lsb; unpack2(tot[i][j], msb, lsb);
                float v = gate(msb) ? __fadd_rn(msb, lsb) : msb;
                v = fmaxf(v, 0.0f);
                o[j] = v;
                vmax = fmaxf(vmax, v);
            }
            float* orow = g_out1 + p * CH + ktile * 128 + tx * 8;
            *reinterpret_cast<float4*>(orow)     = make_float4(o[0], o[1], o[2], o[3]);
            *reinterpret_cast<float4*>(orow + 4) = make_float4(o[4], o[5], o[6], o[7]);
        }
        for (int o = 16; o; o >>= 1) vmax = fmaxf(vmax, __shfl_xor_sync(0xffffffffu, vmax, o));
        if ((t & 31) == 0) atomicMax(&g_scal[3], __float_as_uint(vmax));
    } else {
#pragma unroll
        for (int i = 0; i < 4; ++i) {
            const int p = ptile * 64 + ty * 4 + i;
            const int n2 = p / PIX, q2 = p - n2 * PIX;
#pragma unroll
            for (int j = 0; j < 8; ++j) {
                float msb, lsb; unpack2(tot[i][j], msb, lsb);
                float v = gate(msb) ? __fadd_rn(msb, lsb) : msb;
                const int k = ktile * 128 + tx * 8 + j;
                const int gidx = (n2 * CH + k) * PIX + q2;
                float u = __fadd_rn(v, xres[gidx]);
                outg[gidx] = fmaxf(u, 0.0f);
            }
        }
    }
}

// ---------------------------------------------------------------------------
extern "C" void kernel_launch(void* const* d_in, const int* in_sizes, int n_in,
                              void* d_out, int out_size) {
    const float* x  = (const float*)d_in[0];
    const float* w1 = (const float*)d_in[1];
    const float* w2 = (const float*)d_in[2];
    float* out = (float*)d_out;

    float2* A1; float2* A2; float* W1; float* W2;
    cudaGetSymbolAddress((void**)&A1, g_A1);
    cudaGetSymbolAddress((void**)&A2, g_A2);
    cudaGetSymbolAddress((void**)&W1, g_W1);
    cudaGetSymbolAddress((void**)&W2, g_W2);

    k_init<<<1, 32>>>();
    k_maxabs<<<256, 256>>>(x,  NTOT / 4, 0);
    k_maxabs<<<64,  256>>>(w1, WTOT / 4, 1);
    k_maxabs<<<64,  256>>>(w2, WTOT / 4, 2);

    k_quant_x<<<NTOT / 256, 256>>>(x);
    k_quant_w<<<WTOT / 256, 256>>>(w1, 1, W1);
    k_quant_w<<<WTOT / 256, 256>>>(w2, 2, W2);

    dim3 grid(CH / 128, PTOT / 64);               // (2, 392)
    k_conv<1><<<grid, 256>>>(A1, W1, nullptr, nullptr);   // -> g_out1 + scale
    k_quant_a<<<NTOT / 256, 256>>>();
    k_conv<2><<<grid, 256>>>(A2, W2, x, out);             // -> d_out (NCHW)
}

// round 15
// speedup vs baseline: 1.0755x; 1.0755x over previous
#include <cuda_runtime.h>
#include <math.h>

#define NB 32
#define CH 256
#define HW 28
#define PIX (HW*HW)           // 784
#define PTOT (NB*PIX)         // 25088
#define NTOT (PTOT*CH)        // 6,422,528
#define WTOT (CH*CH*9)        // 589,824

// Eigen threaded-gemm k-panel cap (validated by R14 PASS)
#define KC 320

#define STAGE_BYTES 34304     // sA 64x34 float2 (17408) + sB 32x132 float (16896)
#define SMEM_BYTES  (2 * STAGE_BYTES)

// ---------------- static scratch (no allocation) ---------------------------
__device__ __align__(16) float2 g_A1[NTOT];   // (x_msb, x_lsb) NHWC, layer1
__device__ __align__(16) float2 g_A2[NTOT];   // layer2
__device__ __align__(16) float  g_W1[WTOT];   // wq, [tap][c][k], tap = kh*3+kw
__device__ __align__(16) float  g_W2[WTOT];
__device__ __align__(16) float  g_out1[NTOT]; // relu(pgconv1) NHWC
__device__ unsigned int g_scal[4];            // 0=max|x| 1=max|w1| 2=max|w2| 3=max(out1)

// ---------------------------------------------------------------------------
__global__ void k_init() {
    if (threadIdx.x < 4) g_scal[threadIdx.x] = 0u;
}

__global__ void k_maxabs(const float* __restrict__ p, int n4, int slot) {
    float m = 0.f;
    for (int i = blockIdx.x * blockDim.x + threadIdx.x; i < n4; i += gridDim.x * blockDim.x) {
        float4 v = reinterpret_cast<const float4*>(p)[i];
        m = fmaxf(m, fmaxf(fmaxf(fabsf(v.x), fabsf(v.y)), fmaxf(fabsf(v.z), fabsf(v.w))));
    }
    for (int o = 16; o; o >>= 1) m = fmaxf(m, __shfl_xor_sync(0xffffffffu, m, o));
    if ((threadIdx.x & 31) == 0) atomicMax(&g_scal[slot], __float_as_uint(m));
}

// Mirror of (truncate_msb, quantize_bits, subtraction), reciprocal-multiply
// forms — IDENTICAL to the R14 passing kernel.
__device__ __forceinline__ float2 quant_pair(float v, float S) {
    const float C127R = (float)(1.0 / 127.0);
    float a  = fabsf(v);
    float st = __fadd_rn(S, 1e-8f);
    float sr = __fadd_rn(S, 1e-7f);
    float rt = __fdiv_rn(1.0f, st);
    float rr = __fdiv_rn(1.0f, sr);
    float q1 = floorf(__fmul_rn(__fmul_rn(a, rt), 128.0f));
    float q2 = floorf(__fmul_rn(q1, 0.0625f));                 // /16 exact
    float q4 = __fmul_rn(__fmul_rn(q2, 16.0f), 0.0078125f);    // *16, /128 exact
    float xm = __fmul_rn(q4, st);
    float r  = rintf(__fmul_rn(__fmul_rn(a, rr), 127.0f));     // half-even
    float xq = __fmul_rn(__fmul_rn(r, C127R), sr);
    if (v < 0.0f) { xm = -xm; xq = -xq; }
    return make_float2(xm, __fsub_rn(xq, xm));
}

__global__ void k_quant_x(const float* __restrict__ x) {
    int i = blockIdx.x * blockDim.x + threadIdx.x;
    if (i >= NTOT) return;
    int c = i & 255, p = i >> 8;
    int n = p / PIX, q = p - n * PIX;
    float S = __uint_as_float(g_scal[0]);
    g_A1[i] = quant_pair(x[(n * CH + c) * PIX + q], S);
}

__global__ void k_quant_a() {
    int i = blockIdx.x * blockDim.x + threadIdx.x;
    if (i >= NTOT) return;
    float S = __uint_as_float(g_scal[3]);
    g_A2[i] = quant_pair(g_out1[i], S);
}

__global__ void k_quant_w(const float* __restrict__ w, int slot, float* __restrict__ dst) {
    const float C127R = (float)(1.0 / 127.0);
    int e = blockIdx.x * blockDim.x + threadIdx.x;
    if (e >= WTOT) return;
    int k = e & 255, r = e >> 8;
    int c = r & 255, tap = r >> 8;
    float v = w[(k * CH + c) * 9 + tap];
    float s = __fadd_rn(__uint_as_float(g_scal[slot]), 1e-7f);
    float rs = __fdiv_rn(1.0f, s);
    float q = rintf(__fmul_rn(__fmul_rn(fabsf(v), rs), 127.0f));
    float wq = __fmul_rn(__fmul_rn(q, C127R), s);
    if (v < 0.0f) wq = -wq;
    dst[e] = wq;
}

// ------------------- packed f32x2 helpers (bitwise == scalar) --------------
__device__ __forceinline__ unsigned long long fma2(unsigned long long a,
                                                   unsigned long long b,
                                                   unsigned long long c) {
    unsigned long long d;
    asm("fma.rn.f32x2 %0, %1, %2, %3;" : "=l"(d) : "l"(a), "l"(b), "l"(c));
    return d;
}
__device__ __forceinline__ unsigned long long add2(unsigned long long a,
                                                   unsigned long long b) {
    unsigned long long d;
    asm("add.rn.f32x2 %0, %1, %2;" : "=l"(d) : "l"(a), "l"(b));
    return d;
}
__device__ __forceinline__ unsigned long long dupf(float w) {
    unsigned long long d;
    asm("mov.b64 %0, {%1, %2};" : "=l"(d) : "f"(w), "f"(w));
    return d;
}
__device__ __forceinline__ void unpack2(unsigned long long v, float& lo, float& hi) {
    asm("mov.b64 {%0, %1}, %2;" : "=f"(lo), "=f"(hi) : "l"(v));
}

// Gate: XLA logistic 0.5 + 0.5*tanh(0.5x), XLA f32 tanh rational — unchanged.
__device__ __forceinline__ bool gate(float msb) {
    float x = __fmul_rn(0.5f, msb);
    x = fminf(fmaxf(x, -7.90531110763549805f), 7.90531110763549805f);
    float x2 = __fmul_rn(x, x);
    float p = __fmaf_rn(x2, -2.76076847742355e-16f, 2.00018790482477e-13f);
    p = __fmaf_rn(x2, p, -8.60467152213735e-11f);
    p = __fmaf_rn(x2, p,  5.12229709037114e-08f);
    p = __fmaf_rn(x2, p,  1.48572235717979e-05f);
    p = __fmaf_rn(x2, p,  6.37261928875436e-04f);
    p = __fmaf_rn(x2, p,  4.89352455891786e-03f);
    float num = __fmul_rn(x, p);
    float q = __fmaf_rn(x2, 1.19825839466702e-06f, 1.18534705686654e-04f);
    q = __fmaf_rn(x2, q, 2.26843463243900e-03f);
    q = __fmaf_rn(x2, q, 4.89352518554385e-03f);
    float t = __fdiv_rn(num, q);
    float s = __fadd_rn(0.5f, __fmul_rn(0.5f, t));
    return s > 0.99f;
}

// ---------------------------------------------------------------------------
// Compute one 32-c stage (16 c-pairs). cstar_rel = panel-boundary c (relative
// to this stage's cblk), matching only when in [0,30] even — same flush
// semantics as the R14 passing kernel (numerics identical).
// ---------------------------------------------------------------------------
__device__ __forceinline__ void compute_stage(const float2* __restrict__ A_,
                                              const float* __restrict__ B_,
                                              int cstar_rel, int tx, int ty,
                                              unsigned long long (&acc)[4][8],
                                              unsigned long long (&tot)[4][8]) {
#pragma unroll
    for (int cp = 0; cp < 16; ++cp) {
        if (2 * cp == cstar_rel) {           // kc=320 panel flush (uniform)
#pragma unroll
            for (int i = 0; i < 4; ++i)
#pragma unroll
                for (int j = 0; j < 8; ++j) {
                    tot[i][j] = add2(tot[i][j], acc[i][j]);
                    acc[i][j] = 0ull;
                }
        }
        ulonglong2 av[4];
#pragma unroll
        for (int i = 0; i < 4; ++i)
            av[i] = *reinterpret_cast<const ulonglong2*>(A_ + (ty * 4 + i) * 34 + 2 * cp);
        float w0[8], w1[8];
        *reinterpret_cast<float4*>(&w0[0]) = *reinterpret_cast<const float4*>(B_ + (2*cp    ) * 132 + tx * 8);
        *reinterpret_cast<float4*>(&w0[4]) = *reinterpret_cast<const float4*>(B_ + (2*cp    ) * 132 + tx * 8 + 4);
        *reinterpret_cast<float4*>(&w1[0]) = *reinterpret_cast<const float4*>(B_ + (2*cp + 1) * 132 + tx * 8);
        *reinterpret_cast<float4*>(&w1[4]) = *reinterpret_cast<const float4*>(B_ + (2*cp + 1) * 132 + tx * 8 + 4);
#pragma unroll
        for (int j = 0; j < 8; ++j) {
            unsigned long long p0 = dupf(w0[j]);
            unsigned long long p1 = dupf(w1[j]);
#pragma unroll
            for (int i = 0; i < 4; ++i) {
                acc[i][j] = fma2(av[i].x, p0, acc[i][j]);   // c even
                acc[i][j] = fma2(av[i].y, p1, acc[i][j]);   // c odd
            }
        }
    }
}

// ---------------------------------------------------------------------------
// Dual f32 conv, Eigen-threaded kc=320 accumulation (bit-identical to R14),
// now with a DOUBLE-BUFFERED smem pipeline: one __syncthreads per stage, LDG
// issued 1.5 stages ahead. 72 stages = 9 taps x 8 c-blocks of 32.
// LAYER 2 adds a transposed epilogue through smem for coalesced NCHW stores.
// ---------------------------------------------------------------------------
template <int LAYER>
__global__ void __launch_bounds__(256) k_conv(const float2* __restrict__ Ain,
                                              const float* __restrict__ Win,
                                              const float* __restrict__ xres,
                                              float* __restrict__ outg) {
    extern __shared__ __align__(16) unsigned char dyns[];

    const int t = threadIdx.x, tx = t & 15, ty = t >> 4;
    const int ktile = blockIdx.x;                 // 0..1
    const int ptile = blockIdx.y;                 // 0..391

    const int lp = t >> 2, q4 = t & 3;
    const int gp = ptile * 64 + lp;
    const int n  = gp / PIX, q0 = gp - n * PIX;
    const int py = q0 / HW,  pxx = q0 - py * HW;
    const int crow = t >> 3, koff = (t & 7) * 16;

    unsigned long long acc[4][8], tot[4][8];
#pragma unroll
    for (int i = 0; i < 4; i++)
#pragma unroll
        for (int j = 0; j < 8; j++) { acc[i][j] = 0ull; tot[i][j] = 0ull; }

    float4 ra[4], rb[4];

#define LOAD_STAGE(s) do {                                                          \
    int tap_ = (s) >> 3, cblk_ = ((s) & 7) * 32;                                    \
    int dy_ = tap_ / 3 - 1, dx_ = tap_ - (tap_ / 3) * 3 - 1;                        \
    int yy_ = py + dy_, xx_ = pxx + dx_;                                            \
    bool v_ = ((unsigned)yy_ < (unsigned)HW) && ((unsigned)xx_ < (unsigned)HW);     \
    ra[0] = ra[1] = ra[2] = ra[3] = make_float4(0.f, 0.f, 0.f, 0.f);                \
    if (v_) {                                                                       \
        const float4* sp_ = reinterpret_cast<const float4*>(                        \
            Ain + ((n * HW + yy_) * HW + xx_) * CH + cblk_ + q4 * 8);               \
        ra[0] = sp_[0]; ra[1] = sp_[1]; ra[2] = sp_[2]; ra[3] = sp_[3];             \
    }                                                                               \
    const float4* wp_ = reinterpret_cast<const float4*>(                            \
        Win + (tap_ * CH + cblk_ + crow) * CH + ktile * 128 + koff);                \
    rb[0] = wp_[0]; rb[1] = wp_[1]; rb[2] = wp_[2]; rb[3] = wp_[3];                 \
} while (0)

#define STORE_STAGE(st) do {                                                        \
    float4* da_ = reinterpret_cast<float4*>(                                        \
        (float2*)(dyns + (st) * STAGE_BYTES) + lp * 34 + q4 * 8);                   \
    da_[0] = ra[0]; da_[1] = ra[1]; da_[2] = ra[2]; da_[3] = ra[3];                 \
    float4* db_ = reinterpret_cast<float4*>(                                        \
        (float*)(dyns + (st) * STAGE_BYTES + 17408) + crow * 132 + koff);           \
    db_[0] = rb[0]; db_[1] = rb[1]; db_[2] = rb[2]; db_[3] = rb[3];                 \
} while (0)

    LOAD_STAGE(0);
    STORE_STAGE(0);
    __syncthreads();
    LOAD_STAGE(1);

#pragma unroll 1
    for (int s = 0; s < 72; ++s) {
        const int tap = s >> 3, cblk = (s & 7) * 32;
        const int kb = tap * 256;
        const int cstar_rel = ((kb + KC - 1) / KC) * KC - kb - cblk;
        compute_stage((const float2*)(dyns + (s & 1) * STAGE_BYTES),
                      (const float*)(dyns + (s & 1) * STAGE_BYTES + 17408),
                      cstar_rel, tx, ty, acc, tot);
        if (s + 1 < 72) {
            STORE_STAGE((s + 1) & 1);
            if (s + 2 < 72) LOAD_STAGE(s + 2);
        }
        __syncthreads();
    }

    // final partial panel (gemm-k 2240..2303)
#pragma unroll
    for (int i = 0; i < 4; ++i)
#pragma unroll
        for (int j = 0; j < 8; ++j) tot[i][j] = add2(tot[i][j], acc[i][j]);

    // ------------------------- epilogue ------------------------------------
    if (LAYER == 1) {
        float vmax = 0.f;
#pragma unroll
        for (int i = 0; i < 4; ++i) {
            const int p = ptile * 64 + ty * 4 + i;
            float o[8];
#pragma unroll
            for (int j = 0; j < 8; ++j) {
                float msb, lsb; unpack2(tot[i][j], msb, lsb);
                float v = gate(msb) ? __fadd_rn(msb, lsb) : msb;
                v = fmaxf(v, 0.0f);
                o[j] = v;
                vmax = fmaxf(vmax, v);
            }
            float* orow = g_out1 + p * CH + ktile * 128 + tx * 8;
            *reinterpret_cast<float4*>(orow)     = make_float4(o[0], o[1], o[2], o[3]);
            *reinterpret_cast<float4*>(orow + 4) = make_float4(o[4], o[5], o[6], o[7]);
        }
        for (int o = 16; o; o >>= 1) vmax = fmaxf(vmax, __shfl_xor_sync(0xffffffffu, vmax, o));
        if ((t & 31) == 0) atomicMax(&g_scal[3], __float_as_uint(vmax));
    } else {
        // transpose through smem for coalesced NCHW stores (numerics of each
        // element identical: same gate/fadd/fmax sequence as R14).
        float* sV = (float*)dyns;     // [64 pix][132] floats (33792 B)
#pragma unroll
        for (int i = 0; i < 4; ++i) {
            float o[8];
#pragma unroll
            for (int j = 0; j < 8; ++j) {
                float msb, lsb; unpack2(tot[i][j], msb, lsb);
                o[j] = gate(msb) ? __fadd_rn(msb, lsb) : msb;
            }
            float* vrow = sV + (ty * 4 + i) * 132 + tx * 8;
            *reinterpret_cast<float4*>(vrow)     = make_float4(o[0], o[1], o[2], o[3]);
            *reinterpret_cast<float4*>(vrow + 4) = make_float4(o[4], o[5], o[6], o[7]);
        }
        __syncthreads();
        const int pl2 = t & 63, kq = t >> 6;
        const int gp2 = ptile * 64 + pl2;
        const int n2 = gp2 / PIX, q2 = gp2 - n2 * PIX;
#pragma unroll
        for (int r = 0; r < 32; ++r) {
            const int kl = kq * 32 + r;
            const int gidx = (n2 * CH + ktile * 128 + kl) * PIX + q2;
            float v = sV[pl2 * 132 + kl];
            outg[gidx] = fmaxf(__fadd_rn(v, xres[gidx]), 0.0f);
        }
    }
#undef LOAD_STAGE
#undef STORE_STAGE
}

// ---------------------------------------------------------------------------
extern "C" void kernel_launch(void* const* d_in, const int* in_sizes, int n_in,
                              void* d_out, int out_size) {
    const float* x  = (const float*)d_in[0];
    const float* w1 = (const float*)d_in[1];
    const float* w2 = (const float*)d_in[2];
    float* out = (float*)d_out;

    float2* A1; float2* A2; float* W1; float* W2;
    cudaGetSymbolAddress((void**)&A1, g_A1);
    cudaGetSymbolAddress((void**)&A2, g_A2);
    cudaGetSymbolAddress((void**)&W1, g_W1);
    cudaGetSymbolAddress((void**)&W2, g_W2);

    cudaFuncSetAttribute(k_conv<1>, cudaFuncAttributeMaxDynamicSharedMemorySize, SMEM_BYTES);
    cudaFuncSetAttribute(k_conv<2>, cudaFuncAttributeMaxDynamicSharedMemorySize, SMEM_BYTES);

    k_init<<<1, 32>>>();
    k_maxabs<<<256, 256>>>(x,  NTOT / 4, 0);
    k_maxabs<<<64,  256>>>(w1, WTOT / 4, 1);
    k_maxabs<<<64,  256>>>(w2, WTOT / 4, 2);

    k_quant_x<<<NTOT / 256, 256>>>(x);
    k_quant_w<<<WTOT / 256, 256>>>(w1, 1, W1);
    k_quant_w<<<WTOT / 256, 256>>>(w2, 2, W2);

    dim3 grid(CH / 128, PTOT / 64);               // (2, 392)
    k_conv<1><<<grid, 256, SMEM_BYTES>>>(A1, W1, nullptr, nullptr);
    k_quant_a<<<NTOT / 256, 256>>>();
    k_conv<2><<<grid, 256, SMEM_BYTES>>>(A2, W2, x, out);
}

// round 16
// speedup vs baseline: 1.0844x; 1.0083x over previous
#include <cuda_runtime.h>
#include <math.h>

#define NB 32
#define CH 256
#define HW 28
#define PIX (HW*HW)           // 784
#define PTOT (NB*PIX)         // 25088
#define NTOT (PTOT*CH)        // 6,422,528
#define WTOT (CH*CH*9)        // 589,824

// Eigen threaded-gemm k-panel cap (validated by R14/R15 PASS)
#define KC 320

#define STAGE_BYTES 34304     // sA 64x34 float2 (17408) + sB 32x132 float (16896)
#define SMEM_BYTES  (2 * STAGE_BYTES)

// ---------------- static scratch (no allocation) ---------------------------
__device__ __align__(16) float2 g_A1[NTOT];   // (x_msb, x_lsb) NHWC, layer1
__device__ __align__(16) float2 g_A2[NTOT];   // layer2
__device__ __align__(16) float  g_W1[WTOT];   // wq, [tap][c][k], tap = kh*3+kw
__device__ __align__(16) float  g_W2[WTOT];
__device__ __align__(16) float  g_out1[NTOT]; // relu(pgconv1) NHWC
__device__ unsigned int g_scal[4];            // 0=max|x| 1=max|w1| 2=max|w2| 3=max(out1)

// ---------------------------------------------------------------------------
__global__ void k_init() {
    if (threadIdx.x < 4) g_scal[threadIdx.x] = 0u;
}

// One launch covers x, w1, w2 via blockIdx.y (grid-stride handles size diff).
__global__ void k_maxabs_all(const float* __restrict__ x,
                             const float* __restrict__ w1,
                             const float* __restrict__ w2) {
    const float* p; int n4; int slot = blockIdx.y;
    if (slot == 0)      { p = x;  n4 = NTOT / 4; }
    else if (slot == 1) { p = w1; n4 = WTOT / 4; }
    else                { p = w2; n4 = WTOT / 4; }
    float m = 0.f;
    for (int i = blockIdx.x * blockDim.x + threadIdx.x; i < n4; i += gridDim.x * blockDim.x) {
        float4 v = reinterpret_cast<const float4*>(p)[i];
        m = fmaxf(m, fmaxf(fmaxf(fabsf(v.x), fabsf(v.y)), fmaxf(fabsf(v.z), fabsf(v.w))));
    }
    for (int o = 16; o; o >>= 1) m = fmaxf(m, __shfl_xor_sync(0xffffffffu, m, o));
    if ((threadIdx.x & 31) == 0) atomicMax(&g_scal[slot], __float_as_uint(m));
}

// quant core with hoisted scale-derived constants (pure CSE of the R15 ops:
// st, sr, rt=1/st, rr=1/sr identical since S is uniform; every per-element
// op below is bit-identical to the R15 passing kernel's quant_pair).
__device__ __forceinline__ float2 quant_core(float v, float st, float sr,
                                             float rt, float rr) {
    const float C127R = (float)(1.0 / 127.0);
    float a  = fabsf(v);
    float q1 = floorf(__fmul_rn(__fmul_rn(a, rt), 128.0f));
    float q2 = floorf(__fmul_rn(q1, 0.0625f));
    float q4 = __fmul_rn(__fmul_rn(q2, 16.0f), 0.0078125f);
    float xm = __fmul_rn(q4, st);
    float r  = rintf(__fmul_rn(__fmul_rn(a, rr), 127.0f));
    float xq = __fmul_rn(__fmul_rn(r, C127R), sr);
    if (v < 0.0f) { xm = -xm; xq = -xq; }
    return make_float2(xm, __fsub_rn(xq, xm));
}

// x (NCHW) -> g_A1 (NHWC float2) via 32x32 smem transpose tiles.
// grid (25 qtiles, 8 ctiles, 32 n), block 256.
__global__ void k_quant_x(const float* __restrict__ x) {
    __shared__ float sT[32][33];
    const int n = blockIdx.z, ctile = blockIdx.y, qtile = blockIdx.x;
    const int t = threadIdx.x;
    const float S = __uint_as_float(g_scal[0]);
    const float st = __fadd_rn(S, 1e-8f), sr = __fadd_rn(S, 1e-7f);
    const float rt = __fdiv_rn(1.0f, st), rr = __fdiv_rn(1.0f, sr);

    // load: 32 c-rows x 32 q, coalesced float4 per thread
    {
        const int cl = t >> 3, qg = t & 7;
        const int qb = qtile * 32 + qg * 4;
        if (qb + 3 < PIX) {
            const int c = ctile * 32 + cl;
            float4 v = *reinterpret_cast<const float4*>(x + (n * CH + c) * PIX + qb);
            sT[cl][qg * 4 + 0] = v.x;
            sT[cl][qg * 4 + 1] = v.y;
            sT[cl][qg * 4 + 2] = v.z;
            sT[cl][qg * 4 + 3] = v.w;
        }
    }
    __syncthreads();
    // store: per q-row, 32 c's -> 4 float2 per thread, contiguous NHWC
    {
        const int ql = t >> 3, cg = t & 7;
        const int q = qtile * 32 + ql;
        if (q < PIX) {
            float2* dst = g_A1 + ((n * PIX + q) * CH + ctile * 32 + cg * 4);
#pragma unroll
            for (int i = 0; i < 4; ++i)
                dst[i] = quant_core(sT[cg * 4 + i][ql], st, sr, rt, rr);
        }
    }
}

// relu(out1) (NHWC linear) -> g_A2, 4 elements per thread, hoisted consts.
__global__ void k_quant_a() {
    const float S = __uint_as_float(g_scal[3]);
    const float st = __fadd_rn(S, 1e-8f), sr = __fadd_rn(S, 1e-7f);
    const float rt = __fdiv_rn(1.0f, st), rr = __fdiv_rn(1.0f, sr);
    int i0 = (blockIdx.x * blockDim.x + threadIdx.x) * 4;
    if (i0 >= NTOT) return;
    float4 v = *reinterpret_cast<const float4*>(g_out1 + i0);
    float2* dst = g_A2 + i0;
    dst[0] = quant_core(v.x, st, sr, rt, rr);
    dst[1] = quant_core(v.y, st, sr, rt, rr);
    dst[2] = quant_core(v.z, st, sr, rt, rr);
    dst[3] = quant_core(v.w, st, sr, rt, rr);
}

// w (OIHW) -> wq in [tap][c][k], tap = kh*3+kw; both layers in one launch.
__global__ void k_quant_w_all(const float* __restrict__ w1,
                              const float* __restrict__ w2) {
    const float C127R = (float)(1.0 / 127.0);
    const int which = blockIdx.y;
    const float* w = which ? w2 : w1;
    float* dst = which ? g_W2 : g_W1;
    const float s = __fadd_rn(__uint_as_float(g_scal[which + 1]), 1e-7f);
    const float rs = __fdiv_rn(1.0f, s);
    int e = blockIdx.x * blockDim.x + threadIdx.x;
    if (e >= WTOT) return;
    int k = e & 255, r = e >> 8;
    int c = r & 255, tap = r >> 8;
    float v = w[(k * CH + c) * 9 + tap];
    float q = rintf(__fmul_rn(__fmul_rn(fabsf(v), rs), 127.0f));
    float wq = __fmul_rn(__fmul_rn(q, C127R), s);
    if (v < 0.0f) wq = -wq;
    dst[e] = wq;
}

// ------------------- packed f32x2 helpers (bitwise == scalar) --------------
__device__ __forceinline__ unsigned long long fma2(unsigned long long a,
                                                   unsigned long long b,
                                                   unsigned long long c) {
    unsigned long long d;
    asm("fma.rn.f32x2 %0, %1, %2, %3;" : "=l"(d) : "l"(a), "l"(b), "l"(c));
    return d;
}
__device__ __forceinline__ unsigned long long add2(unsigned long long a,
                                                   unsigned long long b) {
    unsigned long long d;
    asm("add.rn.f32x2 %0, %1, %2;" : "=l"(d) : "l"(a), "l"(b));
    return d;
}
__device__ __forceinline__ unsigned long long dupf(float w) {
    unsigned long long d;
    asm("mov.b64 %0, {%1, %2};" : "=l"(d) : "f"(w), "f"(w));
    return d;
}
__device__ __forceinline__ void unpack2(unsigned long long v, float& lo, float& hi) {
    asm("mov.b64 {%0, %1}, %2;" : "=f"(lo), "=f"(hi) : "l"(v));
}

// Gate: XLA logistic 0.5 + 0.5*tanh(0.5x), XLA f32 tanh rational — unchanged.
__device__ __forceinline__ bool gate(float msb) {
    float x = __fmul_rn(0.5f, msb);
    x = fminf(fmaxf(x, -7.90531110763549805f), 7.90531110763549805f);
    float x2 = __fmul_rn(x, x);
    float p = __fmaf_rn(x2, -2.76076847742355e-16f, 2.00018790482477e-13f);
    p = __fmaf_rn(x2, p, -8.60467152213735e-11f);
    p = __fmaf_rn(x2, p,  5.12229709037114e-08f);
    p = __fmaf_rn(x2, p,  1.48572235717979e-05f);
    p = __fmaf_rn(x2, p,  6.37261928875436e-04f);
    p = __fmaf_rn(x2, p,  4.89352455891786e-03f);
    float num = __fmul_rn(x, p);
    float q = __fmaf_rn(x2, 1.19825839466702e-06f, 1.18534705686654e-04f);
    q = __fmaf_rn(x2, q, 2.26843463243900e-03f);
    q = __fmaf_rn(x2, q, 4.89352518554385e-03f);
    float t = __fdiv_rn(num, q);
    float s = __fadd_rn(0.5f, __fmul_rn(0.5f, t));
    return s > 0.99f;
}

// ---------------------------------------------------------------------------
// compute_stage + k_conv: BYTE-IDENTICAL numerics and structure to R15.
// ---------------------------------------------------------------------------
__device__ __forceinline__ void compute_stage(const float2* __restrict__ A_,
                                              const float* __restrict__ B_,
                                              int cstar_rel, int tx, int ty,
                                              unsigned long long (&acc)[4][8],
                                              unsigned long long (&tot)[4][8]) {
#pragma unroll
    for (int cp = 0; cp < 16; ++cp) {
        if (2 * cp == cstar_rel) {           // kc=320 panel flush (uniform)
#pragma unroll
            for (int i = 0; i < 4; ++i)
#pragma unroll
                for (int j = 0; j < 8; ++j) {
                    tot[i][j] = add2(tot[i][j], acc[i][j]);
                    acc[i][j] = 0ull;
                }
        }
        ulonglong2 av[4];
#pragma unroll
        for (int i = 0; i < 4; ++i)
            av[i] = *reinterpret_cast<const ulonglong2*>(A_ + (ty * 4 + i) * 34 + 2 * cp);
        float w0[8], w1[8];
        *reinterpret_cast<float4*>(&w0[0]) = *reinterpret_cast<const float4*>(B_ + (2*cp    ) * 132 + tx * 8);
        *reinterpret_cast<float4*>(&w0[4]) = *reinterpret_cast<const float4*>(B_ + (2*cp    ) * 132 + tx * 8 + 4);
        *reinterpret_cast<float4*>(&w1[0]) = *reinterpret_cast<const float4*>(B_ + (2*cp + 1) * 132 + tx * 8);
        *reinterpret_cast<float4*>(&w1[4]) = *reinterpret_cast<const float4*>(B_ + (2*cp + 1) * 132 + tx * 8 + 4);
#pragma unroll
        for (int j = 0; j < 8; ++j) {
            unsigned long long p0 = dupf(w0[j]);
            unsigned long long p1 = dupf(w1[j]);
#pragma unroll
            for (int i = 0; i < 4; ++i) {
                acc[i][j] = fma2(av[i].x, p0, acc[i][j]);   // c even
                acc[i][j] = fma2(av[i].y, p1, acc[i][j]);   // c odd
            }
        }
    }
}

template <int LAYER>
__global__ void __launch_bounds__(256) k_conv(const float2* __restrict__ Ain,
                                              const float* __restrict__ Win,
                                              const float* __restrict__ xres,
                                              float* __restrict__ outg) {
    extern __shared__ __align__(16) unsigned char dyns[];

    const int t = threadIdx.x, tx = t & 15, ty = t >> 4;
    const int ktile = blockIdx.x;                 // 0..1
    const int ptile = blockIdx.y;                 // 0..391

    const int lp = t >> 2, q4 = t & 3;
    const int gp = ptile * 64 + lp;
    const int n  = gp / PIX, q0 = gp - n * PIX;
    const int py = q0 / HW,  pxx = q0 - py * HW;
    const int crow = t >> 3, koff = (t & 7) * 16;

    unsigned long long acc[4][8], tot[4][8];
#pragma unroll
    for (int i = 0; i < 4; i++)
#pragma unroll
        for (int j = 0; j < 8; j++) { acc[i][j] = 0ull; tot[i][j] = 0ull; }

    float4 ra[4], rb[4];

#define LOAD_STAGE(s) do {                                                          \
    int tap_ = (s) >> 3, cblk_ = ((s) & 7) * 32;                                    \
    int dy_ = tap_ / 3 - 1, dx_ = tap_ - (tap_ / 3) * 3 - 1;                        \
    int yy_ = py + dy_, xx_ = pxx + dx_;                                            \
    bool v_ = ((unsigned)yy_ < (unsigned)HW) && ((unsigned)xx_ < (unsigned)HW);     \
    ra[0] = ra[1] = ra[2] = ra[3] = make_float4(0.f, 0.f, 0.f, 0.f);                \
    if (v_) {                                                                       \
        const float4* sp_ = reinterpret_cast<const float4*>(                        \
            Ain + ((n * HW + yy_) * HW + xx_) * CH + cblk_ + q4 * 8);               \
        ra[0] = sp_[0]; ra[1] = sp_[1]; ra[2] = sp_[2]; ra[3] = sp_[3];             \
    }                                                                               \
    const float4* wp_ = reinterpret_cast<const float4*>(                            \
        Win + (tap_ * CH + cblk_ + crow) * CH + ktile * 128 + koff);                \
    rb[0] = wp_[0]; rb[1] = wp_[1]; rb[2] = wp_[2]; rb[3] = wp_[3];                 \
} while (0)

#define STORE_STAGE(st) do {                                                        \
    float4* da_ = reinterpret_cast<float4*>(                                        \
        (float2*)(dyns + (st) * STAGE_BYTES) + lp * 34 + q4 * 8);                   \
    da_[0] = ra[0]; da_[1] = ra[1]; da_[2] = ra[2]; da_[3] = ra[3];                 \
    float4* db_ = reinterpret_cast<float4*>(                                        \
        (float*)(dyns + (st) * STAGE_BYTES + 17408) + crow * 132 + koff);           \
    db_[0] = rb[0]; db_[1] = rb[1]; db_[2] = rb[2]; db_[3] = rb[3];                 \
} while (0)

    LOAD_STAGE(0);
    STORE_STAGE(0);
    __syncthreads();
    LOAD_STAGE(1);

#pragma unroll 1
    for (int s = 0; s < 72; ++s) {
        const int tap = s >> 3, cblk = (s & 7) * 32;
        const int kb = tap * 256;
        const int cstar_rel = ((kb + KC - 1) / KC) * KC - kb - cblk;
        compute_stage((const float2*)(dyns + (s & 1) * STAGE_BYTES),
                      (const float*)(dyns + (s & 1) * STAGE_BYTES + 17408),
                      cstar_rel, tx, ty, acc, tot);
        if (s + 1 < 72) {
            STORE_STAGE((s + 1) & 1);
            if (s + 2 < 72) LOAD_STAGE(s + 2);
        }
        __syncthreads();
    }

    // final partial panel (gemm-k 2240..2303)
#pragma unroll
    for (int i = 0; i < 4; ++i)
#pragma unroll
        for (int j = 0; j < 8; ++j) tot[i][j] = add2(tot[i][j], acc[i][j]);

    // ------------------------- epilogue ------------------------------------
    if (LAYER == 1) {
        float vmax = 0.f;
#pragma unroll
        for (int i = 0; i < 4; ++i) {
            const int p = ptile * 64 + ty * 4 + i;
            float o[8];
#pragma unroll
            for (int j = 0; j < 8; ++j) {
                float msb, lsb; unpack2(tot[i][j], msb, lsb);
                float v = gate(msb) ? __fadd_rn(msb, lsb) : msb;
                v = fmaxf(v, 0.0f);
                o[j] = v;
                vmax = fmaxf(vmax, v);
            }
            float* orow = g_out1 + p * CH + ktile * 128 + tx * 8;
            *reinterpret_cast<float4*>(orow)     = make_float4(o[0], o[1], o[2], o[3]);
            *reinterpret_cast<float4*>(orow + 4) = make_float4(o[4], o[5], o[6], o[7]);
        }
        for (int o = 16; o; o >>= 1) vmax = fmaxf(vmax, __shfl_xor_sync(0xffffffffu, vmax, o));
        if ((t & 31) == 0) atomicMax(&g_scal[3], __float_as_uint(vmax));
    } else {
        float* sV = (float*)dyns;     // [64 pix][132] floats
#pragma unroll
        for (int i = 0; i < 4; ++i) {
            float o[8];
#pragma unroll
            for (int j = 0; j < 8; ++j) {
                float msb, lsb; unpack2(tot[i][j], msb, lsb);
                o[j] = gate(msb) ? __fadd_rn(msb, lsb) : msb;
            }
            float* vrow = sV + (ty * 4 + i) * 132 + tx * 8;
            *reinterpret_cast<float4*>(vrow)     = make_float4(o[0], o[1], o[2], o[3]);
            *reinterpret_cast<float4*>(vrow + 4) = make_float4(o[4], o[5], o[6], o[7]);
        }
        __syncthreads();
        const int pl2 = t & 63, kq = t >> 6;
        const int gp2 = ptile * 64 + pl2;
        const int n2 = gp2 / PIX, q2 = gp2 - n2 * PIX;
#pragma unroll
        for (int r = 0; r < 32; ++r) {
            const int kl = kq * 32 + r;
            const int gidx = (n2 * CH + ktile * 128 + kl) * PIX + q2;
            float v = sV[pl2 * 132 + kl];
            outg[gidx] = fmaxf(__fadd_rn(v, xres[gidx]), 0.0f);
        }
    }
#undef LOAD_STAGE
#undef STORE_STAGE
}

// ---------------------------------------------------------------------------
extern "C" void kernel_launch(void* const* d_in, const int* in_sizes, int n_in,
                              void* d_out, int out_size) {
    const float* x  = (const float*)d_in[0];
    const float* w1 = (const float*)d_in[1];
    const float* w2 = (const float*)d_in[2];
    float* out = (float*)d_out;

    float2* A1; float2* A2; float* W1; float* W2;
    cudaGetSymbolAddress((void**)&A1, g_A1);
    cudaGetSymbolAddress((void**)&A2, g_A2);
    cudaGetSymbolAddress((void**)&W1, g_W1);
    cudaGetSymbolAddress((void**)&W2, g_W2);

    cudaFuncSetAttribute(k_conv<1>, cudaFuncAttributeMaxDynamicSharedMemorySize, SMEM_BYTES);
    cudaFuncSetAttribute(k_conv<2>, cudaFuncAttributeMaxDynamicSharedMemorySize, SMEM_BYTES);

    k_init<<<1, 32>>>();
    k_maxabs_all<<<dim3(128, 3), 256>>>(x, w1, w2);
    k_quant_x<<<dim3(25, 8, 32), 256>>>(x);
    k_quant_w_all<<<dim3(WTOT / 256, 2), 256>>>(w1, w2);

    dim3 grid(CH / 128, PTOT / 64);               // (2, 392)
    k_conv<1><<<grid, 256, SMEM_BYTES>>>(A1, W1, nullptr, nullptr);
    k_quant_a<<<NTOT / 1024, 256>>>();
    k_conv<2><<<grid, 256, SMEM_BYTES>>>(A2, W2, x, out);
}

// round 17
// speedup vs baseline: 1.0914x; 1.0065x over previous
#include <cuda_runtime.h>
#include <math.h>

#define NB 32
#define CH 256
#define HW 28
#define PIX (HW*HW)           // 784
#define PTOT (NB*PIX)         // 25088
#define NTOT (PTOT*CH)        // 6,422,528
#define WTOT (CH*CH*9)        // 589,824

// Eigen threaded-gemm k-panel cap (validated by R14/R15/R16 PASS)
#define KC 320

// single-stage smem: sA 64x34 float2 (17408) + sB 32x68 float (8704)
#define SB_OFF  17408
#define SMEM_BYTES 26112

// ---------------- static scratch (no allocation) ---------------------------
__device__ __align__(16) float2 g_A1[NTOT];   // (x_msb, x_lsb) NHWC, layer1
__device__ __align__(16) float2 g_A2[NTOT];   // layer2
__device__ __align__(16) float  g_W1[WTOT];   // wq, [tap][c][k], tap = kh*3+kw
__device__ __align__(16) float  g_W2[WTOT];
__device__ __align__(16) float  g_out1[NTOT]; // relu(pgconv1) NHWC
__device__ unsigned int g_scal[4];            // 0=max|x| 1=max|w1| 2=max|w2| 3=max(out1)

// ---------------------------------------------------------------------------
__global__ void k_init() {
    if (threadIdx.x < 4) g_scal[threadIdx.x] = 0u;
}

__global__ void k_maxabs_all(const float* __restrict__ x,
                             const float* __restrict__ w1,
                             const float* __restrict__ w2) {
    const float* p; int n4; int slot = blockIdx.y;
    if (slot == 0)      { p = x;  n4 = NTOT / 4; }
    else if (slot == 1) { p = w1; n4 = WTOT / 4; }
    else                { p = w2; n4 = WTOT / 4; }
    float m = 0.f;
    for (int i = blockIdx.x * blockDim.x + threadIdx.x; i < n4; i += gridDim.x * blockDim.x) {
        float4 v = reinterpret_cast<const float4*>(p)[i];
        m = fmaxf(m, fmaxf(fmaxf(fabsf(v.x), fabsf(v.y)), fmaxf(fabsf(v.z), fabsf(v.w))));
    }
    for (int o = 16; o; o >>= 1) m = fmaxf(m, __shfl_xor_sync(0xffffffffu, m, o));
    if ((threadIdx.x & 31) == 0) atomicMax(&g_scal[slot], __float_as_uint(m));
}

// quant core — bit-identical ops to the R14/R15/R16 passing kernels.
__device__ __forceinline__ float2 quant_core(float v, float st, float sr,
                                             float rt, float rr) {
    const float C127R = (float)(1.0 / 127.0);
    float a  = fabsf(v);
    float q1 = floorf(__fmul_rn(__fmul_rn(a, rt), 128.0f));
    float q2 = floorf(__fmul_rn(q1, 0.0625f));
    float q4 = __fmul_rn(__fmul_rn(q2, 16.0f), 0.0078125f);
    float xm = __fmul_rn(q4, st);
    float r  = rintf(__fmul_rn(__fmul_rn(a, rr), 127.0f));
    float xq = __fmul_rn(__fmul_rn(r, C127R), sr);
    if (v < 0.0f) { xm = -xm; xq = -xq; }
    return make_float2(xm, __fsub_rn(xq, xm));
}

__global__ void k_quant_x(const float* __restrict__ x) {
    __shared__ float sT[32][33];
    const int n = blockIdx.z, ctile = blockIdx.y, qtile = blockIdx.x;
    const int t = threadIdx.x;
    const float S = __uint_as_float(g_scal[0]);
    const float st = __fadd_rn(S, 1e-8f), sr = __fadd_rn(S, 1e-7f);
    const float rt = __fdiv_rn(1.0f, st), rr = __fdiv_rn(1.0f, sr);
    {
        const int cl = t >> 3, qg = t & 7;
        const int qb = qtile * 32 + qg * 4;
        if (qb + 3 < PIX) {
            const int c = ctile * 32 + cl;
            float4 v = *reinterpret_cast<const float4*>(x + (n * CH + c) * PIX + qb);
            sT[cl][qg * 4 + 0] = v.x;
            sT[cl][qg * 4 + 1] = v.y;
            sT[cl][qg * 4 + 2] = v.z;
            sT[cl][qg * 4 + 3] = v.w;
        }
    }
    __syncthreads();
    {
        const int ql = t >> 3, cg = t & 7;
        const int q = qtile * 32 + ql;
        if (q < PIX) {
            float2* dst = g_A1 + ((n * PIX + q) * CH + ctile * 32 + cg * 4);
#pragma unroll
            for (int i = 0; i < 4; ++i)
                dst[i] = quant_core(sT[cg * 4 + i][ql], st, sr, rt, rr);
        }
    }
}

__global__ void k_quant_a() {
    const float S = __uint_as_float(g_scal[3]);
    const float st = __fadd_rn(S, 1e-8f), sr = __fadd_rn(S, 1e-7f);
    const float rt = __fdiv_rn(1.0f, st), rr = __fdiv_rn(1.0f, sr);
    int i0 = (blockIdx.x * blockDim.x + threadIdx.x) * 4;
    if (i0 >= NTOT) return;
    float4 v = *reinterpret_cast<const float4*>(g_out1 + i0);
    float2* dst = g_A2 + i0;
    dst[0] = quant_core(v.x, st, sr, rt, rr);
    dst[1] = quant_core(v.y, st, sr, rt, rr);
    dst[2] = quant_core(v.z, st, sr, rt, rr);
    dst[3] = quant_core(v.w, st, sr, rt, rr);
}

__global__ void k_quant_w_all(const float* __restrict__ w1,
                              const float* __restrict__ w2) {
    const float C127R = (float)(1.0 / 127.0);
    const int which = blockIdx.y;
    const float* w = which ? w2 : w1;
    float* dst = which ? g_W2 : g_W1;
    const float s = __fadd_rn(__uint_as_float(g_scal[which + 1]), 1e-7f);
    const float rs = __fdiv_rn(1.0f, s);
    int e = blockIdx.x * blockDim.x + threadIdx.x;
    if (e >= WTOT) return;
    int k = e & 255, r = e >> 8;
    int c = r & 255, tap = r >> 8;
    float v = w[(k * CH + c) * 9 + tap];
    float q = rintf(__fmul_rn(__fmul_rn(fabsf(v), rs), 127.0f));
    float wq = __fmul_rn(__fmul_rn(q, C127R), s);
    if (v < 0.0f) wq = -wq;
    dst[e] = wq;
}

// ------------------- packed f32x2 helpers (bitwise == scalar) --------------
__device__ __forceinline__ unsigned long long fma2(unsigned long long a,
                                                   unsigned long long b,
                                                   unsigned long long c) {
    unsigned long long d;
    asm("fma.rn.f32x2 %0, %1, %2, %3;" : "=l"(d) : "l"(a), "l"(b), "l"(c));
    return d;
}
__device__ __forceinline__ unsigned long long add2(unsigned long long a,
                                                   unsigned long long b) {
    unsigned long long d;
    asm("add.rn.f32x2 %0, %1, %2;" : "=l"(d) : "l"(a), "l"(b));
    return d;
}
__device__ __forceinline__ unsigned long long dupf(float w) {
    unsigned long long d;
    asm("mov.b64 %0, {%1, %2};" : "=l"(d) : "f"(w), "f"(w));
    return d;
}
__device__ __forceinline__ void unpack2(unsigned long long v, float& lo, float& hi) {
    asm("mov.b64 {%0, %1}, %2;" : "=f"(lo), "=f"(hi) : "l"(v));
}

// Gate — unchanged (XLA logistic rational).
__device__ __forceinline__ bool gate(float msb) {
    float x = __fmul_rn(0.5f, msb);
    x = fminf(fmaxf(x, -7.90531110763549805f), 7.90531110763549805f);
    float x2 = __fmul_rn(x, x);
    float p = __fmaf_rn(x2, -2.76076847742355e-16f, 2.00018790482477e-13f);
    p = __fmaf_rn(x2, p, -8.60467152213735e-11f);
    p = __fmaf_rn(x2, p,  5.12229709037114e-08f);
    p = __fmaf_rn(x2, p,  1.48572235717979e-05f);
    p = __fmaf_rn(x2, p,  6.37261928875436e-04f);
    p = __fmaf_rn(x2, p,  4.89352455891786e-03f);
    float num = __fmul_rn(x, p);
    float q = __fmaf_rn(x2, 1.19825839466702e-06f, 1.18534705686654e-04f);
    q = __fmaf_rn(x2, q, 2.26843463243900e-03f);
    q = __fmaf_rn(x2, q, 4.89352518554385e-03f);
    float t = __fdiv_rn(num, q);
    float s = __fadd_rn(0.5f, __fmul_rn(0.5f, t));
    return s > 0.99f;
}

// ---------------------------------------------------------------------------
// Dual f32 conv, Eigen-threaded kc=320 accumulation — same chain & flush
// semantics as R14-R16 (bit-identical per-output arithmetic). New tiling:
// 64 pix x 64 k per CTA (grid 4 x 392 = 1568 blocks), thread tile 4x4,
// single-stage smem, 2 CTAs/SM for latency smoothing + wave granularity.
// ---------------------------------------------------------------------------
template <int LAYER>
__global__ void __launch_bounds__(256, 2) k_conv(const float2* __restrict__ Ain,
                                                 const float* __restrict__ Win,
                                                 const float* __restrict__ xres,
                                                 float* __restrict__ outg) {
    extern __shared__ __align__(16) unsigned char dyns[];
    float2* sA = (float2*)dyns;                 // [64 pix][34]
    float*  sB = (float*)(dyns + SB_OFF);       // [32 c][68]

    const int t = threadIdx.x, tx = t & 15, ty = t >> 4;
    const int ktile = blockIdx.x;               // 0..3 (64 k each)
    const int ptile = blockIdx.y;               // 0..391

    const int lp = t >> 2, q4 = t & 3;          // A loader: pixel row, quarter
    const int gp = ptile * 64 + lp;
    const int n  = gp / PIX, q0 = gp - n * PIX;
    const int py = q0 / HW,  pxx = q0 - py * HW;
    const int crow = t >> 3, koff = (t & 7) * 8;  // B loader: c row, k offset

    unsigned long long acc[4][4], tot[4][4];
#pragma unroll
    for (int i = 0; i < 4; i++)
#pragma unroll
        for (int j = 0; j < 4; j++) { acc[i][j] = 0ull; tot[i][j] = 0ull; }

#pragma unroll 1
    for (int s = 0; s < 72; ++s) {
        const int tap = s >> 3, cblk = (s & 7) * 32;
        const int dy = tap / 3 - 1, dx = tap - (tap / 3) * 3 - 1;   // kh-major
        const int yy = py + dy, xx = pxx + dx;
        const bool valid = ((unsigned)yy < (unsigned)HW) && ((unsigned)xx < (unsigned)HW);

        // global loads (before barrier, overlap with partner CTA's compute)
        float4 ra0 = {0,0,0,0}, ra1 = {0,0,0,0}, ra2 = {0,0,0,0}, ra3 = {0,0,0,0};
        if (valid) {
            const float4* sp = reinterpret_cast<const float4*>(
                Ain + ((n * HW + yy) * HW + xx) * CH + cblk + q4 * 8);
            ra0 = sp[0]; ra1 = sp[1]; ra2 = sp[2]; ra3 = sp[3];
        }
        const float4* wp = reinterpret_cast<const float4*>(
            Win + (tap * CH + cblk + crow) * CH + ktile * 64 + koff);
        float4 rb0 = wp[0], rb1 = wp[1];

        __syncthreads();                        // previous stage compute done
        {
            float4* da = reinterpret_cast<float4*>(sA + lp * 34 + q4 * 8);
            da[0] = ra0; da[1] = ra1; da[2] = ra2; da[3] = ra3;
            float4* db = reinterpret_cast<float4*>(sB + crow * 68 + koff);
            db[0] = rb0; db[1] = rb1;
        }
        __syncthreads();

        const int kb = tap * 256;
        const int cstar_rel = ((kb + KC - 1) / KC) * KC - kb - cblk;

#pragma unroll
        for (int cp = 0; cp < 16; ++cp) {       // c-pairs, ascending (c fastest)
            if (2 * cp == cstar_rel) {          // kc=320 panel flush (uniform)
#pragma unroll
                for (int i = 0; i < 4; ++i)
#pragma unroll
                    for (int j = 0; j < 4; ++j) {
                        tot[i][j] = add2(tot[i][j], acc[i][j]);
                        acc[i][j] = 0ull;
                    }
            }
            ulonglong2 av[4];
#pragma unroll
            for (int i = 0; i < 4; ++i)
                av[i] = *reinterpret_cast<const ulonglong2*>(sA + (ty * 4 + i) * 34 + 2 * cp);
            float4 b0 = *reinterpret_cast<const float4*>(sB + (2*cp    ) * 68 + tx * 4);
            float4 b1 = *reinterpret_cast<const float4*>(sB + (2*cp + 1) * 68 + tx * 4);
            const float* b0f = (const float*)&b0;
            const float* b1f = (const float*)&b1;
#pragma unroll
            for (int j = 0; j < 4; ++j) {
                unsigned long long p0 = dupf(b0f[j]);
                unsigned long long p1 = dupf(b1f[j]);
#pragma unroll
                for (int i = 0; i < 4; ++i) {
                    acc[i][j] = fma2(av[i].x, p0, acc[i][j]);   // c even
                    acc[i][j] = fma2(av[i].y, p1, acc[i][j]);   // c odd
                }
            }
        }
    }

    // final partial panel (gemm-k 2240..2303)
#pragma unroll
    for (int i = 0; i < 4; ++i)
#pragma unroll
        for (int j = 0; j < 4; ++j) tot[i][j] = add2(tot[i][j], acc[i][j]);

    // ------------------------- epilogue ------------------------------------
    if (LAYER == 1) {
        float vmax = 0.f;
#pragma unroll
        for (int i = 0; i < 4; ++i) {
            const int p = ptile * 64 + ty * 4 + i;
            float o[4];
#pragma unroll
            for (int j = 0; j < 4; ++j) {
                float msb, lsb; unpack2(tot[i][j], msb, lsb);
                float v = gate(msb) ? __fadd_rn(msb, lsb) : msb;
                v = fmaxf(v, 0.0f);
                o[j] = v;
                vmax = fmaxf(vmax, v);
            }
            *reinterpret_cast<float4*>(g_out1 + p * CH + ktile * 64 + tx * 4) =
                make_float4(o[0], o[1], o[2], o[3]);
        }
        for (int o = 16; o; o >>= 1) vmax = fmaxf(vmax, __shfl_xor_sync(0xffffffffu, vmax, o));
        if ((t & 31) == 0) atomicMax(&g_scal[3], __float_as_uint(vmax));
    } else {
        float* sV = (float*)dyns;               // [64 pix][68] floats (17408 B)
        __syncthreads();                        // mainloop smem reads done
#pragma unroll
        for (int i = 0; i < 4; ++i) {
            float o[4];
#pragma unroll
            for (int j = 0; j < 4; ++j) {
                float msb, lsb; unpack2(tot[i][j], msb, lsb);
                o[j] = gate(msb) ? __fadd_rn(msb, lsb) : msb;
            }
            *reinterpret_cast<float4*>(sV + (ty * 4 + i) * 68 + tx * 4) =
                make_float4(o[0], o[1], o[2], o[3]);
        }
        __syncthreads();
        const int pl2 = t & 63, kq = t >> 6;
        const int gp2 = ptile * 64 + pl2;
        const int n2 = gp2 / PIX, q2 = gp2 - n2 * PIX;
#pragma unroll
        for (int r = 0; r < 16; ++r) {
            const int kl = kq * 16 + r;
            const int gidx = (n2 * CH + ktile * 64 + kl) * PIX + q2;
            float v = sV[pl2 * 68 + kl];
            outg[gidx] = fmaxf(__fadd_rn(v, xres[gidx]), 0.0f);
        }
    }
}

// ---------------------------------------------------------------------------
extern "C" void kernel_launch(void* const* d_in, const int* in_sizes, int n_in,
                              void* d_out, int out_size) {
    const float* x  = (const float*)d_in[0];
    const float* w1 = (const float*)d_in[1];
    const float* w2 = (const float*)d_in[2];
    float* out = (float*)d_out;

    float2* A1; float2* A2; float* W1; float* W2;
    cudaGetSymbolAddress((void**)&A1, g_A1);
    cudaGetSymbolAddress((void**)&A2, g_A2);
    cudaGetSymbolAddress((void**)&W1, g_W1);
    cudaGetSymbolAddress((void**)&W2, g_W2);

    cudaFuncSetAttribute(k_conv<1>, cudaFuncAttributeMaxDynamicSharedMemorySize, SMEM_BYTES);
    cudaFuncSetAttribute(k_conv<2>, cudaFuncAttributeMaxDynamicSharedMemorySize, SMEM_BYTES);

    k_init<<<1, 32>>>();
    k_maxabs_all<<<dim3(128, 3), 256>>>(x, w1, w2);
    k_quant_x<<<dim3(25, 8, 32), 256>>>(x);
    k_quant_w_all<<<dim3(WTOT / 256, 2), 256>>>(w1, w2);

    dim3 grid(CH / 64, PTOT / 64);              // (4, 392) = 1568 blocks
    k_conv<1><<<grid, 256, SMEM_BYTES>>>(A1, W1, nullptr, nullptr);
    k_quant_a<<<NTOT / 1024, 256>>>();
    k_conv<2><<<grid, 256, SMEM_BYTES>>>(A2, W2, x, out);
}